// round 7
// baseline (speedup 1.0000x reference)
#include <cuda_runtime.h>
#include <cuda_bf16.h>

typedef unsigned long long ull;

#define BB 8
#define NP 8192
#define NQ 1024
#define KNN 32
#define F1 64

#define FPS_C 4                    // CTAs per cluster (per batch)
#define FPS_T 256                  // threads per CTA
#define FPS_OWN (NP / FPS_C)       // 2048 points owned per CTA

// scratch: neighbor indices (radius-resolved), B*N2*K
__device__ int g_nbr[BB * NQ * KNN];

// ---------------- packed f32x2 helpers ----------------
union F2 { ull u; float2 f; };

__device__ __forceinline__ ull add2(ull a, ull b)
{
    ull r; asm("add.rn.f32x2 %0, %1, %2;" : "=l"(r) : "l"(a), "l"(b)); return r;
}
__device__ __forceinline__ ull mul2(ull a, ull b)
{
    ull r; asm("mul.rn.f32x2 %0, %1, %2;" : "=l"(r) : "l"(a), "l"(b)); return r;
}
__device__ __forceinline__ void fma2(ull& d, ull a, ull b)
{
    asm("fma.rn.f32x2 %0, %1, %2, %0;" : "+l"(d) : "l"(a), "l"(b));
}
__device__ __forceinline__ ull bc2(float x)
{
    ull r; asm("mov.b64 %0, {%1, %1};" : "=l"(r) : "f"(x)); return r;
}
__device__ __forceinline__ float2 unpk(ull r)
{
    float2 v; asm("mov.b64 {%0, %1}, %2;" : "=f"(v.x), "=f"(v.y) : "l"(r)); return v;
}
__device__ __forceinline__ float lrelu(float x) { return fmaxf(x, 0.2f * x); }

// ---------------- cluster / mbarrier helpers ----------------
__device__ __forceinline__ unsigned smem_u32(const void* p)
{
    unsigned a;
    asm("{ .reg .u64 t; cvta.to.shared.u64 t, %1; cvt.u32.u64 %0, t; }"
        : "=r"(a) : "l"(p));
    return a;
}
__device__ __forceinline__ unsigned ctarank()
{
    unsigned r; asm("mov.u32 %0, %%cluster_ctarank;" : "=r"(r)); return r;
}
__device__ __forceinline__ void mbar_init(unsigned addr, unsigned cnt)
{
    asm volatile("mbarrier.init.shared.b64 [%0], %1;" :: "r"(addr), "r"(cnt) : "memory");
}
__device__ __forceinline__ void st_cluster_u64(unsigned addr, unsigned rank, ull v)
{
    asm volatile(
        "{ .reg .b32 r; mapa.shared::cluster.u32 r, %0, %1;"
        " st.shared::cluster.u64 [r], %2; }"
        :: "r"(addr), "r"(rank), "l"(v) : "memory");
}
// RELEASE at CLUSTER scope: orders this thread's prior remote stores for any
// consumer that acquire-waits on this barrier at cluster scope.
__device__ __forceinline__ void arrive_cluster(unsigned addr, unsigned rank)
{
    asm volatile(
        "{ .reg .b32 r; mapa.shared::cluster.u32 r, %0, %1;"
        " mbarrier.arrive.release.cluster.shared::cluster.b64 _, [r]; }"
        :: "r"(addr), "r"(rank) : "memory");
}
// ACQUIRE at CLUSTER scope: makes peer CTAs' released stores visible.
__device__ __forceinline__ void mbar_wait(unsigned addr, unsigned par)
{
    asm volatile(
        "{ .reg .pred P;\n"
        "WL%=: mbarrier.try_wait.parity.acquire.cluster.shared::cta.b64 P, [%0], %1;\n"
        "@!P bra WL%=;\n}"
        :: "r"(addr), "r"(par) : "memory");
}
__device__ __forceinline__ void cluster_sync()
{
    asm volatile("barrier.cluster.arrive.aligned;" ::: "memory");
    asm volatile("barrier.cluster.wait.aligned;" ::: "memory");
}
__device__ __forceinline__ ull umax64(ull a, ull b) { return a > b ? a : b; }

// ---------------------------------------------------------------------------
// Kernel 1: FPS, cluster-parallel. 4 CTAs x 256 threads per batch,
// 8 pts/thread in registers. Per-step cross-CTA argmax via DSMEM slots +
// mbarrier (count=4, release/acquire at cluster scope).
// Key = (d2bits<<13)|(8191-gidx): u64 max == argmax with exact
// lowest-global-index tie semantics. Float math identical to validated R5.
// ---------------------------------------------------------------------------
__global__ void __launch_bounds__(FPS_T, 1) __cluster_dims__(FPS_C, 1, 1)
fps_kernel(const float* __restrict__ xyz, float* __restrict__ out)
{
    extern __shared__ float s[];            // sx/sy/sz: full 8192 pts = 96KB
    float* sx = s;
    float* sy = s + NP;
    float* sz = s + 2 * NP;
    __shared__ ull swk[FPS_T / 32];          // per-warp partial keys (8)
    __shared__ ull slots[2][FPS_C];          // double-buffered cluster partials
    __shared__ float curv[3];
    __shared__ alignas(8) ull mbar_store;

    const int t = threadIdx.x;
    const int lane = t & 31;
    const int wid = t >> 5;
    const unsigned rank = ctarank();
    const int b = blockIdx.x >> 2;           // 4 CTAs per batch
    const float* p = xyz + (size_t)b * NP * 3;

    const unsigned mbar = smem_u32(&mbar_store);
    const unsigned slot0 = smem_u32(&slots[0][0]);

    // full coordinate copy (for winner lookup by any CTA)
    for (int i = t; i < NP; i += FPS_T) {
        sx[i] = p[i * 3 + 0];
        sy[i] = p[i * 3 + 1];
        sz[i] = p[i * 3 + 2];
    }

    // own 2048 points in registers (packed pairs)
    const int obase = rank * FPS_OWN;
    ull px[4], py[4], pz[4];
    float md[8];
#pragma unroll
    for (int i = 0; i < 4; i++) {
        int i0 = obase + t + (2 * i) * FPS_T;
        int i1 = obase + t + (2 * i + 1) * FPS_T;
        F2 X, Y, Z;
        X.f.x = p[i0 * 3 + 0]; Y.f.x = p[i0 * 3 + 1]; Z.f.x = p[i0 * 3 + 2];
        X.f.y = p[i1 * 3 + 0]; Y.f.y = p[i1 * 3 + 1]; Z.f.y = p[i1 * 3 + 2];
        px[i] = X.u; py[i] = Y.u; pz[i] = Z.u;
        md[2 * i] = 3.402823466e38f;
        md[2 * i + 1] = 3.402823466e38f;
    }
    if (t == 0) {
        curv[0] = p[0]; curv[1] = p[1]; curv[2] = p[2];
        mbar_init(mbar, FPS_C);
        if (rank == 0) {
            float* o = out + (size_t)b * NQ * 3;
            o[0] = p[0]; o[1] = p[1]; o[2] = p[2];
        }
    }
    __syncthreads();
    cluster_sync();                          // mbar init visible cluster-wide

    unsigned par = 0;
    for (int si = 1; si < NQ; si++) {
        const ull ncx = bc2(-curv[0]);
        const ull ncy = bc2(-curv[1]);
        const ull ncz = bc2(-curv[2]);
        float tv = -1.0f;
#pragma unroll
        for (int i = 0; i < 4; i++) {
            ull dx = add2(px[i], ncx);
            ull dy = add2(py[i], ncy);
            ull dz = add2(pz[i], ncz);
            ull d = mul2(dx, dx);
            fma2(d, dy, dy);
            fma2(d, dz, dz);
            float2 D = unpk(d);
            md[2 * i]     = fminf(md[2 * i], D.x);
            md[2 * i + 1] = fminf(md[2 * i + 1], D.y);
            tv = fmaxf(tv, md[2 * i]);
            tv = fmaxf(tv, md[2 * i + 1]);
        }
        // branch-free lowest-slot scan: global idx = obase + t + i*256,
        // lower i -> lower global idx for this thread
        int bi = 0;
#pragma unroll
        for (int i = 7; i >= 0; i--)
            if (md[i] == tv) bi = i;
        const int gidx = obase + t + (bi << 8);
        ull key = ((ull)__float_as_uint(tv) << 13) | (unsigned)(8191 - gidx);
#pragma unroll
        for (int o = 16; o > 0; o >>= 1)
            key = umax64(key, __shfl_xor_sync(0xffffffffu, key, o));
        if (lane == 0) swk[wid] = key;
        __syncthreads();                                   // BAR_A
        if (wid == 0) {
            ull k = (lane < FPS_T / 32) ? swk[lane] : 0ull;
#pragma unroll
            for (int o = 4; o > 0; o >>= 1)
                k = umax64(k, __shfl_xor_sync(0xffffffffu, k, o));
            if (lane == 0) {
                const unsigned myslot = slot0 + ((si & 1) * FPS_C + rank) * 8;
#pragma unroll
                for (int r = 0; r < FPS_C; r++) st_cluster_u64(myslot, r, k);
#pragma unroll
                for (int r = 0; r < FPS_C; r++) arrive_cluster(mbar, r);
                mbar_wait(mbar, par);
                ull m = slots[si & 1][0];
                m = umax64(m, slots[si & 1][1]);
                m = umax64(m, slots[si & 1][2]);
                m = umax64(m, slots[si & 1][3]);
                const int widx = 8191 - (int)(m & 0x1fffu);
                const float wx = sx[widx], wy = sy[widx], wz = sz[widx];
                curv[0] = wx; curv[1] = wy; curv[2] = wz;
                if (rank == 0) {
                    float* o2 = out + (size_t)b * NQ * 3 + si * 3;
                    o2[0] = wx; o2[1] = wy; o2[2] = wz;
                }
            }
        }
        par ^= 1;
        __syncthreads();                                   // BAR_B
    }
    cluster_sync();                          // no CTA exits with peers mid-DSMEM
}

// ---------------------------------------------------------------------------
// Kernel 2: warp-per-query 32-NN, radius pre-prune, append-then-sort.
// (unchanged from validated R5)
// ---------------------------------------------------------------------------
__device__ __forceinline__ void isort(ull* a, int n)
{
    for (int i = 1; i < n; i++) {
        ull k = a[i];
        int m = i;
        while (m > 0 && a[m - 1] > k) { a[m] = a[m - 1]; m--; }
        a[m] = k;
    }
}

__global__ void __launch_bounds__(256) knn_kernel(const float* __restrict__ xyz,
                                                  const float* __restrict__ outxyz)
{
    __shared__ float4 sp[1024];                 // 16KB tile

    const int warp = threadIdx.x >> 5;
    const int lane = threadIdx.x & 31;
    const int gq = blockIdx.x * 8 + warp;       // global query id
    const int b = blockIdx.x >> 7;              // 128 blocks per batch

    const float qx = outxyz[gq * 3 + 0];
    const float qy = outxyz[gq * 3 + 1];
    const float qz = outxyz[gq * 3 + 2];
    const float q2 = fmaf(qx, qx, fmaf(qy, qy, qz * qz));

    ull arr[KNN];
    int cnt = 0;
    ull klim = ~0ull;
    bool sorted = false;
    const float r2 = 0.04f;

    const float* p = xyz + (size_t)b * NP * 3;

    for (int tile = 0; tile < 8; tile++) {
        const int base = tile << 10;
        for (int j = threadIdx.x; j < 1024; j += 256) {
            float x = p[(base + j) * 3 + 0];
            float y = p[(base + j) * 3 + 1];
            float z = p[(base + j) * 3 + 2];
            sp[j] = make_float4(x, y, z, fmaf(x, x, fmaf(y, y, z * z)));
        }
        __syncthreads();
#pragma unroll 4
        for (int jj = 0; jj < 32; jj++) {
            const int j = (jj << 5) + lane;
            float4 P = sp[j];
            float qp = fmaf(qx, P.x, fmaf(qy, P.y, qz * P.z));
            float d2 = fmaf(-2.0f, qp, q2 + P.w);
            if (d2 <= r2) {                                  // radius pre-prune
                unsigned du = __float_as_uint(d2);
                du ^= (unsigned)((int)du >> 31) | 0x80000000u;
                ull key = ((ull)du << 32) | (unsigned)(base + j);
                if (!sorted) {
                    arr[cnt++] = key;                        // cheap append
                    if (cnt == KNN) { isort(arr, KNN); klim = arr[KNN - 1]; sorted = true; }
                } else if (key < klim) {                     // rare overflow path
                    int m = KNN - 1;
                    while (m > 0 && arr[m - 1] > key) { arr[m] = arr[m - 1]; m--; }
                    arr[m] = key;
                    klim = arr[KNN - 1];
                }
            }
        }
        __syncthreads();
    }
    if (!sorted) isort(arr, cnt);

    // exact warp merge: 32 rounds of extract-min over per-lane sorted lists
    ull h = (cnt > 0) ? arr[0] : ~0ull;
    int ptr = 1;
    int nearidx = 0;
    int* dst = g_nbr + (size_t)gq * KNN;
    for (int k = 0; k < KNN; k++) {
        ull m = h;
#pragma unroll
        for (int o = 16; o > 0; o >>= 1) {
            ull x = __shfl_xor_sync(0xffffffffu, m, o);
            if (x < m) m = x;
        }
        if (k == 0) nearidx = (int)(m & 0xffffffffu);    // self always within radius
        int wi = (m == ~0ull) ? nearidx : (int)(m & 0xffffffffu);
        if (lane == k) dst[k] = wi;
        if (h == m && m != ~0ull)
            h = (ptr < cnt) ? arr[ptr++] : ~0ull;
    }
}

// ---------------------------------------------------------------------------
// Kernel 3: gather + MLP(67->64->64->128, leaky 0.2) + max over K (unchanged).
// ---------------------------------------------------------------------------
template <int NU>
__device__ __forceinline__ void accum_row(ull* acc, const float* wrow, float xc)
{
    ull xv = bc2(xc);
    const ulonglong2* w = (const ulonglong2*)wrow;
#pragma unroll
    for (int jj = 0; jj < NU / 2; jj++) {
        ulonglong2 ww = w[jj];
        fma2(acc[2 * jj + 0], xv, ww.x);
        fma2(acc[2 * jj + 1], xv, ww.y);
    }
}

#define OW0 0
#define OB0 4288
#define OW1 4352
#define OB1 8448
#define OW2 8512
#define OB2 16704
#define OPOOL 16832
#define SMEM_MLP_FLOATS (OPOOL + 4 * 128)
#define SMEM_MLP_BYTES (SMEM_MLP_FLOATS * 4)

__global__ void __launch_bounds__(128, 3) mlp_kernel(
    const float* __restrict__ xyz, const float* __restrict__ feat,
    const float* __restrict__ W0, const float* __restrict__ b0,
    const float* __restrict__ W1, const float* __restrict__ b1,
    const float* __restrict__ W2, const float* __restrict__ b2,
    float* __restrict__ out)
{
    extern __shared__ float sm[];
    for (int i = threadIdx.x; i < OPOOL; i += 128) {
        float v;
        if (i < OB0)        v = W0[i];
        else if (i < OW1)   v = b0[i - OB0];
        else if (i < OB1)   v = W1[i - OW1];
        else if (i < OW2)   v = b1[i - OB1];
        else if (i < OB2)   v = W2[i - OW2];
        else                v = b2[i - OB2];
        sm[i] = v;
    }
    __syncthreads();

    const int warp = threadIdx.x >> 5;
    const int lane = threadIdx.x & 31;
    const int q = blockIdx.x * 4 + warp;
    const int b = q >> 10;

    const int nidx = g_nbr[q * KNN + lane];
    const float cx = out[q * 3 + 0];
    const float cy = out[q * 3 + 1];
    const float cz = out[q * 3 + 2];
    const float* pp = xyz + ((size_t)b * NP + nidx) * 3;
    const float x0 = pp[0] - cx;
    const float x1 = pp[1] - cy;
    const float x2 = pp[2] - cz;
    const float4* pf = (const float4*)(feat + ((size_t)b * NP + nidx) * F1);

    // ---- layer 1: 67 -> 64 ----
    ull a1[32];
    {
        const ull* bb = (const ull*)(sm + OB0);
#pragma unroll
        for (int j = 0; j < 32; j++) a1[j] = bb[j];
    }
    accum_row<32>(a1, sm + OW0 + 0 * 64, x0);
    accum_row<32>(a1, sm + OW0 + 1 * 64, x1);
    accum_row<32>(a1, sm + OW0 + 2 * 64, x2);
#pragma unroll
    for (int g = 0; g < 16; g++) {
        float4 f = pf[g];
        accum_row<32>(a1, sm + OW0 + (3 + 4 * g + 0) * 64, f.x);
        accum_row<32>(a1, sm + OW0 + (3 + 4 * g + 1) * 64, f.y);
        accum_row<32>(a1, sm + OW0 + (3 + 4 * g + 2) * 64, f.z);
        accum_row<32>(a1, sm + OW0 + (3 + 4 * g + 3) * 64, f.w);
    }
    float h1[64];
#pragma unroll
    for (int j = 0; j < 32; j++) {
        float2 v = unpk(a1[j]);
        h1[2 * j + 0] = lrelu(v.x);
        h1[2 * j + 1] = lrelu(v.y);
    }

    // ---- layer 2: 64 -> 64 ----
    ull a2[32];
    {
        const ull* bb = (const ull*)(sm + OB1);
#pragma unroll
        for (int j = 0; j < 32; j++) a2[j] = bb[j];
    }
#pragma unroll
    for (int c = 0; c < 64; c++) accum_row<32>(a2, sm + OW1 + c * 64, h1[c]);
    float h2[64];
#pragma unroll
    for (int j = 0; j < 32; j++) {
        float2 v = unpk(a2[j]);
        h2[2 * j + 0] = lrelu(v.x);
        h2[2 * j + 1] = lrelu(v.y);
    }

    // ---- layer 3: 64 -> 128, 4 chunks of 32, fused warp max-pool ----
    float* pool = sm + OPOOL + warp * 128;
#pragma unroll
    for (int ch = 0; ch < 4; ch++) {
        ull a3[16];
        {
            const ull* bb = (const ull*)(sm + OB2);
#pragma unroll
            for (int j = 0; j < 16; j++) a3[j] = bb[ch * 16 + j];
        }
#pragma unroll
        for (int c = 0; c < 64; c++)
            accum_row<16>(a3, sm + OW2 + c * 128 + ch * 32, h2[c]);
#pragma unroll
        for (int j = 0; j < 16; j++) {
            float2 v = unpk(a3[j]);
            float v0 = lrelu(v.x);
            float v1 = lrelu(v.y);
#pragma unroll
            for (int o = 16; o > 0; o >>= 1) {
                v0 = fmaxf(v0, __shfl_down_sync(0xffffffffu, v0, o));
                v1 = fmaxf(v1, __shfl_down_sync(0xffffffffu, v1, o));
            }
            if (lane == 0) {
                pool[ch * 32 + 2 * j + 0] = v0;
                pool[ch * 32 + 2 * j + 1] = v1;
            }
        }
    }
    __syncwarp();
    float4* dst = (float4*)(out + BB * NQ * 3 + (size_t)q * 128);
    dst[lane] = ((const float4*)pool)[lane];
}

// ---------------------------------------------------------------------------
extern "C" void kernel_launch(void* const* d_in, const int* in_sizes, int n_in,
                              void* d_out, int out_size)
{
    const float* xyz  = (const float*)d_in[0];
    const float* feat = (const float*)d_in[1];
    const float* W0   = (const float*)d_in[2];
    const float* b0   = (const float*)d_in[3];
    const float* W1   = (const float*)d_in[4];
    const float* b1   = (const float*)d_in[5];
    const float* W2   = (const float*)d_in[6];
    const float* b2   = (const float*)d_in[7];
    float* out = (float*)d_out;

    cudaFuncSetAttribute(fps_kernel, cudaFuncAttributeMaxDynamicSharedMemorySize,
                         3 * NP * 4);
    cudaFuncSetAttribute(mlp_kernel, cudaFuncAttributeMaxDynamicSharedMemorySize,
                         SMEM_MLP_BYTES);

    fps_kernel<<<BB * FPS_C, FPS_T, 3 * NP * 4>>>(xyz, out);
    knn_kernel<<<(BB * NQ) / 8, 256>>>(xyz, out);
    mlp_kernel<<<(BB * NQ) / 4, 128, SMEM_MLP_BYTES>>>(xyz, feat, W0, b0, W1, b1,
                                                       W2, b2, out);
}

// round 8
// speedup vs baseline: 1.2758x; 1.2758x over previous
#include <cuda_runtime.h>
#include <cuda_bf16.h>

typedef unsigned long long ull;

#define BB 8
#define NP 8192
#define NQ 1024
#define KNN 32
#define F1 64

// scratch: neighbor indices (radius-resolved), B*N2*K
__device__ int g_nbr[BB * NQ * KNN];
// FPS progress counters (count of selected points published), reset per launch
__device__ int g_prog[BB];

#define FUSED_SMEM_BYTES (116 * 1024)   // >= 96KB needed; forces 1 block/SM

// ---------------- packed f32x2 helpers (MLP) ----------------
__device__ __forceinline__ void fma2(ull& d, ull a, ull b)
{
    asm("fma.rn.f32x2 %0, %1, %2, %0;" : "+l"(d) : "l"(a), "l"(b));
}
__device__ __forceinline__ ull bc2(float x)
{
    ull r; asm("mov.b64 %0, {%1, %1};" : "=l"(r) : "f"(x)); return r;
}
__device__ __forceinline__ float2 unpk(ull r)
{
    float2 v; asm("mov.b64 {%0, %1}, %2;" : "=f"(v.x), "=f"(v.y) : "l"(r)); return v;
}
__device__ __forceinline__ float lrelu(float x) { return fmaxf(x, 0.2f * x); }

// ---------------- acquire/release helpers ----------------
__device__ __forceinline__ int ld_acq(const int* p)
{
    int v;
    asm volatile("ld.acquire.gpu.b32 %0, [%1];" : "=r"(v) : "l"(p) : "memory");
    return v;
}
__device__ __forceinline__ void st_rel(int* p, int v)
{
    asm volatile("st.release.gpu.b32 [%0], %1;" :: "l"(p), "r"(v) : "memory");
}

// ---------------------------------------------------------------------------
// FPS part (R3/R4 structure — measured 690us): 1024 threads, 8 pts/thread,
// shuffle-carried (value,index) argmax, 2 barriers/step.
// Publishes progress to g_prog[b] every 32 steps (release).
// ---------------------------------------------------------------------------
__device__ void fps_part(float* s, const float* __restrict__ xyz,
                         float* __restrict__ out)
{
    float* sx = s;
    float* sy = s + NP;
    float* sz = s + 2 * NP;
    __shared__ float swv[32];
    __shared__ int   swi[32];
    __shared__ float cur[3];

    const int b = blockIdx.x;
    const int t = threadIdx.x;
    const float* p = xyz + (size_t)b * NP * 3;

    float px[8], py[8], pz[8], md[8];
#pragma unroll
    for (int i = 0; i < 8; i++) {
        int pi = t + i * 1024;
        float x = p[pi * 3 + 0];
        float y = p[pi * 3 + 1];
        float z = p[pi * 3 + 2];
        px[i] = x; py[i] = y; pz[i] = z;
        sx[pi] = x; sy[pi] = y; sz[pi] = z;
        md[i] = 3.402823466e38f;
    }
    __syncthreads();

    float* oxyz = out + (size_t)b * NQ * 3;
    if (t == 0) {
        cur[0] = sx[0]; cur[1] = sy[0]; cur[2] = sz[0];
        oxyz[0] = sx[0]; oxyz[1] = sy[0]; oxyz[2] = sz[0];
    }
    __syncthreads();

    for (int si = 1; si < NQ; si++) {
        float cx = cur[0], cy = cur[1], cz = cur[2];
        float bv = -1.0f;
        int   bi = 0;
#pragma unroll
        for (int i = 0; i < 8; i++) {
            float dx = px[i] - cx;
            float dy = py[i] - cy;
            float dz = pz[i] - cz;
            float d = dx * dx + dy * dy + dz * dz;
            float m = fminf(md[i], d);
            md[i] = m;
            if (m > bv) { bv = m; bi = t + i * 1024; }
        }
        // warp argmax (tie -> lower index)
#pragma unroll
        for (int o = 16; o > 0; o >>= 1) {
            float ov = __shfl_down_sync(0xffffffffu, bv, o);
            int   oi = __shfl_down_sync(0xffffffffu, bi, o);
            if (ov > bv || (ov == bv && oi < bi)) { bv = ov; bi = oi; }
        }
        if ((t & 31) == 0) { swv[t >> 5] = bv; swi[t >> 5] = bi; }
        __syncthreads();
        if (t < 32) {
            bv = swv[t]; bi = swi[t];
#pragma unroll
            for (int o = 16; o > 0; o >>= 1) {
                float ov = __shfl_down_sync(0xffffffffu, bv, o);
                int   oi = __shfl_down_sync(0xffffffffu, bi, o);
                if (ov > bv || (ov == bv && oi < bi)) { bv = ov; bi = oi; }
            }
            if (t == 0) {
                float wx = sx[bi], wy = sy[bi], wz = sz[bi];
                cur[0] = wx; cur[1] = wy; cur[2] = wz;
                oxyz[si * 3 + 0] = wx;
                oxyz[si * 3 + 1] = wy;
                oxyz[si * 3 + 2] = wz;
                if ((si & 31) == 31)
                    st_rel(&g_prog[b], si + 1);   // orders prior out[] stores
            }
        }
        __syncthreads();
    }
}

// ---------------------------------------------------------------------------
// KNN part (validated R5 logic): 32 warps = 32 queries per block.
// Gated on FPS progress for its query group.
// ---------------------------------------------------------------------------
__device__ __forceinline__ void isort(ull* a, int n)
{
    for (int i = 1; i < n; i++) {
        ull k = a[i];
        int m = i;
        while (m > 0 && a[m - 1] > k) { a[m] = a[m - 1]; m--; }
        a[m] = k;
    }
}

__device__ void knn_part(float* s, const float* __restrict__ xyz,
                         const float* __restrict__ outxyz)
{
    float4* sp = (float4*)s;                    // 1024 float4 = 16KB

    const int bk = blockIdx.x - BB;             // 0..255
    const int b = bk >> 5;                      // batch
    const int grp = bk & 31;                    // query group within batch
    const int warp = threadIdx.x >> 5;
    const int lane = threadIdx.x & 31;
    const int gq = b * NQ + grp * 32 + warp;    // this warp's query

    // gate: need centers for queries grp*32 .. grp*32+31
    if (threadIdx.x == 0) {
        const int need = (grp + 1) * 32;
        while (ld_acq(&g_prog[b]) < need) __nanosleep(128);
    }
    __syncthreads();

    const float qx = outxyz[gq * 3 + 0];
    const float qy = outxyz[gq * 3 + 1];
    const float qz = outxyz[gq * 3 + 2];
    const float q2 = fmaf(qx, qx, fmaf(qy, qy, qz * qz));

    ull arr[KNN];                               // local mem, sorted ascending
    int cnt = 0;
    ull klim = ~0ull;
    bool sorted = false;
    const float r2 = 0.04f;

    const float* p = xyz + (size_t)b * NP * 3;

    for (int tile = 0; tile < 8; tile++) {
        const int base = tile << 10;
        {
            const int j = threadIdx.x;          // 1024 threads, 1024 points
            float x = p[(base + j) * 3 + 0];
            float y = p[(base + j) * 3 + 1];
            float z = p[(base + j) * 3 + 2];
            sp[j] = make_float4(x, y, z, fmaf(x, x, fmaf(y, y, z * z)));
        }
        __syncthreads();
#pragma unroll 4
        for (int jj = 0; jj < 32; jj++) {
            const int j = (jj << 5) + lane;
            float4 P = sp[j];
            float qp = fmaf(qx, P.x, fmaf(qy, P.y, qz * P.z));
            float d2 = fmaf(-2.0f, qp, q2 + P.w);
            if (d2 <= r2) {                                  // radius pre-prune
                unsigned du = __float_as_uint(d2);
                du ^= (unsigned)((int)du >> 31) | 0x80000000u;
                ull key = ((ull)du << 32) | (unsigned)(base + j);
                if (!sorted) {
                    arr[cnt++] = key;                        // cheap append
                    if (cnt == KNN) { isort(arr, KNN); klim = arr[KNN - 1]; sorted = true; }
                } else if (key < klim) {                     // rare overflow path
                    int m = KNN - 1;
                    while (m > 0 && arr[m - 1] > key) { arr[m] = arr[m - 1]; m--; }
                    arr[m] = key;
                    klim = arr[KNN - 1];
                }
            }
        }
        __syncthreads();
    }
    if (!sorted) isort(arr, cnt);

    // exact warp merge: 32 rounds of extract-min over per-lane sorted lists
    ull h = (cnt > 0) ? arr[0] : ~0ull;
    int ptr = 1;
    int nearidx = 0;
    int* dst = g_nbr + (size_t)gq * KNN;
    for (int k = 0; k < KNN; k++) {
        ull m = h;
#pragma unroll
        for (int o = 16; o > 0; o >>= 1) {
            ull x = __shfl_xor_sync(0xffffffffu, m, o);
            if (x < m) m = x;
        }
        if (k == 0) nearidx = (int)(m & 0xffffffffu);    // self always within radius
        int wi = (m == ~0ull) ? nearidx : (int)(m & 0xffffffffu);
        if (lane == k) dst[k] = wi;
        if (h == m && m != ~0ull)
            h = (ptr < cnt) ? arr[ptr++] : ~0ull;
    }
}

__global__ void __launch_bounds__(1024, 1) fused_kernel(
    const float* __restrict__ xyz, float* __restrict__ out)
{
    extern __shared__ float s[];
    if (blockIdx.x < BB) fps_part(s, xyz, out);
    else                 knn_part(s, xyz, out);
}

// ---------------------------------------------------------------------------
// Kernel 3: gather + MLP(67->64->64->128, leaky 0.2) + max over K (unchanged).
// ---------------------------------------------------------------------------
template <int NU>
__device__ __forceinline__ void accum_row(ull* acc, const float* wrow, float xc)
{
    ull xv = bc2(xc);
    const ulonglong2* w = (const ulonglong2*)wrow;
#pragma unroll
    for (int jj = 0; jj < NU / 2; jj++) {
        ulonglong2 ww = w[jj];
        fma2(acc[2 * jj + 0], xv, ww.x);
        fma2(acc[2 * jj + 1], xv, ww.y);
    }
}

#define OW0 0
#define OB0 4288
#define OW1 4352
#define OB1 8448
#define OW2 8512
#define OB2 16704
#define OPOOL 16832
#define SMEM_MLP_FLOATS (OPOOL + 4 * 128)
#define SMEM_MLP_BYTES (SMEM_MLP_FLOATS * 4)

__global__ void __launch_bounds__(128, 3) mlp_kernel(
    const float* __restrict__ xyz, const float* __restrict__ feat,
    const float* __restrict__ W0, const float* __restrict__ b0,
    const float* __restrict__ W1, const float* __restrict__ b1,
    const float* __restrict__ W2, const float* __restrict__ b2,
    float* __restrict__ out)
{
    extern __shared__ float sm[];
    for (int i = threadIdx.x; i < OPOOL; i += 128) {
        float v;
        if (i < OB0)        v = W0[i];
        else if (i < OW1)   v = b0[i - OB0];
        else if (i < OB1)   v = W1[i - OW1];
        else if (i < OW2)   v = b1[i - OB1];
        else if (i < OB2)   v = W2[i - OW2];
        else                v = b2[i - OB2];
        sm[i] = v;
    }
    __syncthreads();

    const int warp = threadIdx.x >> 5;
    const int lane = threadIdx.x & 31;
    const int q = blockIdx.x * 4 + warp;
    const int b = q >> 10;

    const int nidx = g_nbr[q * KNN + lane];
    const float cx = out[q * 3 + 0];
    const float cy = out[q * 3 + 1];
    const float cz = out[q * 3 + 2];
    const float* pp = xyz + ((size_t)b * NP + nidx) * 3;
    const float x0 = pp[0] - cx;
    const float x1 = pp[1] - cy;
    const float x2 = pp[2] - cz;
    const float4* pf = (const float4*)(feat + ((size_t)b * NP + nidx) * F1);

    // ---- layer 1: 67 -> 64 ----
    ull a1[32];
    {
        const ull* bb = (const ull*)(sm + OB0);
#pragma unroll
        for (int j = 0; j < 32; j++) a1[j] = bb[j];
    }
    accum_row<32>(a1, sm + OW0 + 0 * 64, x0);
    accum_row<32>(a1, sm + OW0 + 1 * 64, x1);
    accum_row<32>(a1, sm + OW0 + 2 * 64, x2);
#pragma unroll
    for (int g = 0; g < 16; g++) {
        float4 f = pf[g];
        accum_row<32>(a1, sm + OW0 + (3 + 4 * g + 0) * 64, f.x);
        accum_row<32>(a1, sm + OW0 + (3 + 4 * g + 1) * 64, f.y);
        accum_row<32>(a1, sm + OW0 + (3 + 4 * g + 2) * 64, f.z);
        accum_row<32>(a1, sm + OW0 + (3 + 4 * g + 3) * 64, f.w);
    }
    float h1[64];
#pragma unroll
    for (int j = 0; j < 32; j++) {
        float2 v = unpk(a1[j]);
        h1[2 * j + 0] = lrelu(v.x);
        h1[2 * j + 1] = lrelu(v.y);
    }

    // ---- layer 2: 64 -> 64 ----
    ull a2[32];
    {
        const ull* bb = (const ull*)(sm + OB1);
#pragma unroll
        for (int j = 0; j < 32; j++) a2[j] = bb[j];
    }
#pragma unroll
    for (int c = 0; c < 64; c++) accum_row<32>(a2, sm + OW1 + c * 64, h1[c]);
    float h2[64];
#pragma unroll
    for (int j = 0; j < 32; j++) {
        float2 v = unpk(a2[j]);
        h2[2 * j + 0] = lrelu(v.x);
        h2[2 * j + 1] = lrelu(v.y);
    }

    // ---- layer 3: 64 -> 128, 4 chunks of 32, fused warp max-pool ----
    float* pool = sm + OPOOL + warp * 128;
#pragma unroll
    for (int ch = 0; ch < 4; ch++) {
        ull a3[16];
        {
            const ull* bb = (const ull*)(sm + OB2);
#pragma unroll
            for (int j = 0; j < 16; j++) a3[j] = bb[ch * 16 + j];
        }
#pragma unroll
        for (int c = 0; c < 64; c++)
            accum_row<16>(a3, sm + OW2 + c * 128 + ch * 32, h2[c]);
#pragma unroll
        for (int j = 0; j < 16; j++) {
            float2 v = unpk(a3[j]);
            float v0 = lrelu(v.x);
            float v1 = lrelu(v.y);
#pragma unroll
            for (int o = 16; o > 0; o >>= 1) {
                v0 = fmaxf(v0, __shfl_down_sync(0xffffffffu, v0, o));
                v1 = fmaxf(v1, __shfl_down_sync(0xffffffffu, v1, o));
            }
            if (lane == 0) {
                pool[ch * 32 + 2 * j + 0] = v0;
                pool[ch * 32 + 2 * j + 1] = v1;
            }
        }
    }
    __syncwarp();
    float4* dst = (float4*)(out + BB * NQ * 3 + (size_t)q * 128);
    dst[lane] = ((const float4*)pool)[lane];
}

// ---------------------------------------------------------------------------
extern "C" void kernel_launch(void* const* d_in, const int* in_sizes, int n_in,
                              void* d_out, int out_size)
{
    const float* xyz  = (const float*)d_in[0];
    const float* feat = (const float*)d_in[1];
    const float* W0   = (const float*)d_in[2];
    const float* b0   = (const float*)d_in[3];
    const float* W1   = (const float*)d_in[4];
    const float* b1   = (const float*)d_in[5];
    const float* W2   = (const float*)d_in[6];
    const float* b2   = (const float*)d_in[7];
    float* out = (float*)d_out;

    cudaFuncSetAttribute(fused_kernel, cudaFuncAttributeMaxDynamicSharedMemorySize,
                         FUSED_SMEM_BYTES);
    cudaFuncSetAttribute(mlp_kernel, cudaFuncAttributeMaxDynamicSharedMemorySize,
                         SMEM_MLP_BYTES);

    // reset progress counters on every call/replay (capture-legal stream op)
    void* paddr = nullptr;
    cudaGetSymbolAddress(&paddr, g_prog);
    cudaMemsetAsync(paddr, 0, sizeof(int) * BB);

    fused_kernel<<<BB + BB * 32, 1024, FUSED_SMEM_BYTES>>>(xyz, out);
    mlp_kernel<<<(BB * NQ) / 4, 128, SMEM_MLP_BYTES>>>(xyz, feat, W0, b0, W1, b1,
                                                       W2, b2, out);
}

// round 9
// speedup vs baseline: 1.7737x; 1.3903x over previous
#include <cuda_runtime.h>
#include <cuda_bf16.h>

typedef unsigned long long ull;

#define BB 8
#define NP 8192
#define NQ 1024
#define KNN 32
#define F1 64

// scratch: neighbor indices (radius-resolved), B*N2*K
__device__ int g_nbr[BB * NQ * KNN];

// ---------------- packed f32x2 helpers ----------------
union F2 { ull u; float2 f; };

__device__ __forceinline__ ull add2(ull a, ull b)
{
    ull r; asm("add.rn.f32x2 %0, %1, %2;" : "=l"(r) : "l"(a), "l"(b)); return r;
}
__device__ __forceinline__ ull mul2(ull a, ull b)
{
    ull r; asm("mul.rn.f32x2 %0, %1, %2;" : "=l"(r) : "l"(a), "l"(b)); return r;
}
__device__ __forceinline__ void fma2(ull& d, ull a, ull b)
{
    asm("fma.rn.f32x2 %0, %1, %2, %0;" : "+l"(d) : "l"(a), "l"(b));
}
__device__ __forceinline__ ull bc2(float x)
{
    ull r; asm("mov.b64 %0, {%1, %1};" : "=l"(r) : "f"(x)); return r;
}
__device__ __forceinline__ float2 unpk(ull r)
{
    float2 v; asm("mov.b64 {%0, %1}, %2;" : "=f"(v.x), "=f"(v.y) : "l"(r)); return v;
}
__device__ __forceinline__ float lrelu(float x) { return fmaxf(x, 0.2f * x); }

// ---------------------------------------------------------------------------
// Kernel 1: FPS. 1 block/batch, 1024 threads, 8 pts/thread (packed f32x2
// distance math = validated R5 numerics). Argmax via REDUX.SYNC:
//   hi = warp redux-max of d2 bits (non-negative floats: uint order == float)
//   lo = warp redux-min of matching global index (exact lowest-index ties)
// then one 32-slot stage in warp 0. cur[] holds NEGATED coords.
// ---------------------------------------------------------------------------
__global__ void __launch_bounds__(1024) fps_kernel(const float* __restrict__ xyz,
                                                   float* __restrict__ out)
{
    extern __shared__ float s[];            // sx/sy/sz: 3*8192 floats = 96KB
    float* sx = s;
    float* sy = s + NP;
    float* sz = s + 2 * NP;
    __shared__ unsigned swh[32];
    __shared__ int      swl[32];
    __shared__ float cur[4];

    const int b = blockIdx.x;
    const int t = threadIdx.x;
    const int lane = t & 31;
    const int wid = t >> 5;
    const float* p = xyz + (size_t)b * NP * 3;

    ull px[4], py[4], pz[4];
    float md[8];
#pragma unroll
    for (int i = 0; i < 4; i++) {
        int i0 = t + (2 * i) * 1024;
        int i1 = t + (2 * i + 1) * 1024;
        F2 X, Y, Z;
        X.f.x = p[i0 * 3 + 0]; Y.f.x = p[i0 * 3 + 1]; Z.f.x = p[i0 * 3 + 2];
        X.f.y = p[i1 * 3 + 0]; Y.f.y = p[i1 * 3 + 1]; Z.f.y = p[i1 * 3 + 2];
        px[i] = X.u; py[i] = Y.u; pz[i] = Z.u;
        sx[i0] = X.f.x; sy[i0] = Y.f.x; sz[i0] = Z.f.x;
        sx[i1] = X.f.y; sy[i1] = Y.f.y; sz[i1] = Z.f.y;
        md[2 * i] = 3.402823466e38f;
        md[2 * i + 1] = 3.402823466e38f;
    }
    if (t == 0) {
        cur[0] = -p[0]; cur[1] = -p[1]; cur[2] = -p[2];
        float* o = out + (size_t)b * NQ * 3;
        o[0] = p[0]; o[1] = p[1]; o[2] = p[2];
    }
    __syncthreads();

    for (int si = 1; si < NQ; si++) {
        const ull ncx = bc2(cur[0]), ncy = bc2(cur[1]), ncz = bc2(cur[2]);
        float tv = -1.0f;
#pragma unroll
        for (int i = 0; i < 4; i++) {
            ull dx = add2(px[i], ncx);
            ull dy = add2(py[i], ncy);
            ull dz = add2(pz[i], ncz);
            ull d = mul2(dx, dx);
            fma2(d, dy, dy);
            fma2(d, dz, dz);
            float2 D = unpk(d);
            md[2 * i]     = fminf(md[2 * i], D.x);
            md[2 * i + 1] = fminf(md[2 * i + 1], D.y);
            tv = fmaxf(tv, md[2 * i]);
            tv = fmaxf(tv, md[2 * i + 1]);
        }
        // warp argmax via redux (all md >= 0 -> uint order == float order)
        const unsigned hi = __reduce_max_sync(0xffffffffu, __float_as_uint(tv));
        int cand = 0x7fffffff;
#pragma unroll
        for (int i = 7; i >= 0; i--)
            if (__float_as_uint(md[i]) == hi) cand = t + (i << 10);
        const unsigned lo = __reduce_min_sync(0xffffffffu, (unsigned)cand);
        if (lane == 0) { swh[wid] = hi; swl[wid] = (int)lo; }
        __syncthreads();                                   // (1)
        if (t < 32) {
            const unsigned h2 = swh[t];
            const unsigned hh = __reduce_max_sync(0xffffffffu, h2);
            const unsigned c2 = (h2 == hh) ? (unsigned)swl[t] : 0x7fffffffu;
            const unsigned l2 = __reduce_min_sync(0xffffffffu, c2);
            if (t == 0) {
                const int id = (int)l2;
                const float wx = sx[id], wy = sy[id], wz = sz[id];
                cur[0] = -wx; cur[1] = -wy; cur[2] = -wz;
                float* o2 = out + (size_t)b * NQ * 3 + si * 3;
                o2[0] = wx; o2[1] = wy; o2[2] = wz;
            }
        }
        __syncthreads();                                   // (2)
    }
}

// ---------------------------------------------------------------------------
// Kernel 2: warp-per-query 32-NN, radius pre-prune, append-then-sort.
// (unchanged from validated R5; ~25us)
// ---------------------------------------------------------------------------
__device__ __forceinline__ void isort(ull* a, int n)
{
    for (int i = 1; i < n; i++) {
        ull k = a[i];
        int m = i;
        while (m > 0 && a[m - 1] > k) { a[m] = a[m - 1]; m--; }
        a[m] = k;
    }
}

__global__ void __launch_bounds__(256) knn_kernel(const float* __restrict__ xyz,
                                                  const float* __restrict__ outxyz)
{
    __shared__ float4 sp[1024];                 // 16KB tile

    const int warp = threadIdx.x >> 5;
    const int lane = threadIdx.x & 31;
    const int gq = blockIdx.x * 8 + warp;       // global query id
    const int b = blockIdx.x >> 7;              // 128 blocks per batch

    const float qx = outxyz[gq * 3 + 0];
    const float qy = outxyz[gq * 3 + 1];
    const float qz = outxyz[gq * 3 + 2];
    const float q2 = fmaf(qx, qx, fmaf(qy, qy, qz * qz));

    ull arr[KNN];
    int cnt = 0;
    ull klim = ~0ull;
    bool sorted = false;
    const float r2 = 0.04f;

    const float* p = xyz + (size_t)b * NP * 3;

    for (int tile = 0; tile < 8; tile++) {
        const int base = tile << 10;
        for (int j = threadIdx.x; j < 1024; j += 256) {
            float x = p[(base + j) * 3 + 0];
            float y = p[(base + j) * 3 + 1];
            float z = p[(base + j) * 3 + 2];
            sp[j] = make_float4(x, y, z, fmaf(x, x, fmaf(y, y, z * z)));
        }
        __syncthreads();
#pragma unroll 4
        for (int jj = 0; jj < 32; jj++) {
            const int j = (jj << 5) + lane;
            float4 P = sp[j];
            float qp = fmaf(qx, P.x, fmaf(qy, P.y, qz * P.z));
            float d2 = fmaf(-2.0f, qp, q2 + P.w);
            if (d2 <= r2) {                                  // radius pre-prune
                unsigned du = __float_as_uint(d2);
                du ^= (unsigned)((int)du >> 31) | 0x80000000u;
                ull key = ((ull)du << 32) | (unsigned)(base + j);
                if (!sorted) {
                    arr[cnt++] = key;                        // cheap append
                    if (cnt == KNN) { isort(arr, KNN); klim = arr[KNN - 1]; sorted = true; }
                } else if (key < klim) {                     // rare overflow path
                    int m = KNN - 1;
                    while (m > 0 && arr[m - 1] > key) { arr[m] = arr[m - 1]; m--; }
                    arr[m] = key;
                    klim = arr[KNN - 1];
                }
            }
        }
        __syncthreads();
    }
    if (!sorted) isort(arr, cnt);

    // exact warp merge: 32 rounds of extract-min over per-lane sorted lists
    ull h = (cnt > 0) ? arr[0] : ~0ull;
    int ptr = 1;
    int nearidx = 0;
    int* dst = g_nbr + (size_t)gq * KNN;
    for (int k = 0; k < KNN; k++) {
        ull m = h;
#pragma unroll
        for (int o = 16; o > 0; o >>= 1) {
            ull x = __shfl_xor_sync(0xffffffffu, m, o);
            if (x < m) m = x;
        }
        if (k == 0) nearidx = (int)(m & 0xffffffffu);    // self always within radius
        int wi = (m == ~0ull) ? nearidx : (int)(m & 0xffffffffu);
        if (lane == k) dst[k] = wi;
        if (h == m && m != ~0ull)
            h = (ptr < cnt) ? arr[ptr++] : ~0ull;
    }
}

// ---------------------------------------------------------------------------
// Kernel 3 v2: gather + MLP(67->64->64->128, leaky 0.2) + max over K.
// 2 warps per query: warp half h computes output channels [h*32, h*32+32)
// (layer3: [h*64, h*64+64) in 2 chunks). Activations exchanged via padded
// shared (stride 65 -> conflict-free). Accumulation order per output channel
// identical to the validated kernel => bit-identical results.
// Regs ~80 (vs 168) -> 16 warps/SM.
// ---------------------------------------------------------------------------
template <int NU>
__device__ __forceinline__ void accum_row(ull* acc, const float* wrow, float xc)
{
    ull xv = bc2(xc);
    const ulonglong2* w = (const ulonglong2*)wrow;
#pragma unroll
    for (int jj = 0; jj < NU / 2; jj++) {
        ulonglong2 ww = w[jj];
        fma2(acc[2 * jj + 0], xv, ww.x);
        fma2(acc[2 * jj + 1], xv, ww.y);
    }
}

#define OW0 0
#define OB0 4288
#define OW1 4352
#define OB1 8448
#define OW2 8512
#define OB2 16704
#define OHBUF 16832                       // h exchange: 4 queries * 32 n * 65
#define OPOOLV2 (OHBUF + 4 * 32 * 65)     // 25152
#define SMEM_MLP_FLOATS (OPOOLV2 + 4 * 128)
#define SMEM_MLP_BYTES (SMEM_MLP_FLOATS * 4)

__global__ void __launch_bounds__(256, 2) mlp_kernel(
    const float* __restrict__ xyz, const float* __restrict__ feat,
    const float* __restrict__ W0, const float* __restrict__ b0,
    const float* __restrict__ W1, const float* __restrict__ b1,
    const float* __restrict__ W2, const float* __restrict__ b2,
    float* __restrict__ out)
{
    extern __shared__ float sm[];
    // cooperative weight staging
    for (int i = threadIdx.x; i < OHBUF; i += 256) {
        float v;
        if (i < OB0)        v = W0[i];
        else if (i < OW1)   v = b0[i - OB0];
        else if (i < OB1)   v = W1[i - OW1];
        else if (i < OW2)   v = b1[i - OB1];
        else if (i < OB2)   v = W2[i - OW2];
        else                v = b2[i - OB2];
        sm[i] = v;
    }

    const int warp = threadIdx.x >> 5;
    const int lane = threadIdx.x & 31;
    const int qlocal = warp >> 1;             // 0..3
    const int half = warp & 1;                // output-half owned by this warp
    const int q = blockIdx.x * 4 + qlocal;
    const int b = q >> 10;

    const int nidx = g_nbr[q * KNN + lane];
    const float cx = out[q * 3 + 0];
    const float cy = out[q * 3 + 1];
    const float cz = out[q * 3 + 2];
    const float* pp = xyz + ((size_t)b * NP + nidx) * 3;
    const float x0 = pp[0] - cx;
    const float x1 = pp[1] - cy;
    const float x2 = pp[2] - cz;
    const float4* pf = (const float4*)(feat + ((size_t)b * NP + nidx) * F1);

    float* hq = sm + OHBUF + qlocal * (32 * 65);   // [neighbor][65]
    const int hrow = lane * 65;
    __syncthreads();                                // weights staged

    // ---- layer 1: 67 -> 64, this warp computes outs [half*32, half*32+32) ----
    ull a1[16];
    {
        const ull* bb = (const ull*)(sm + OB0) + half * 16;
#pragma unroll
        for (int j = 0; j < 16; j++) a1[j] = bb[j];
    }
    const int w0off = OW0 + half * 32;
    accum_row<16>(a1, sm + w0off + 0 * 64, x0);
    accum_row<16>(a1, sm + w0off + 1 * 64, x1);
    accum_row<16>(a1, sm + w0off + 2 * 64, x2);
#pragma unroll
    for (int g = 0; g < 16; g++) {
        float4 f = pf[g];
        accum_row<16>(a1, sm + w0off + (3 + 4 * g + 0) * 64, f.x);
        accum_row<16>(a1, sm + w0off + (3 + 4 * g + 1) * 64, f.y);
        accum_row<16>(a1, sm + w0off + (3 + 4 * g + 2) * 64, f.z);
        accum_row<16>(a1, sm + w0off + (3 + 4 * g + 3) * 64, f.w);
    }
#pragma unroll
    for (int j = 0; j < 16; j++) {
        float2 v = unpk(a1[j]);
        hq[hrow + half * 32 + 2 * j + 0] = lrelu(v.x);
        hq[hrow + half * 32 + 2 * j + 1] = lrelu(v.y);
    }
    __syncthreads();                                // h1 complete

    // ---- layer 2: 64 -> 64 (outs [half*32, half*32+32)) ----
    ull a2[16];
    {
        const ull* bb = (const ull*)(sm + OB1) + half * 16;
#pragma unroll
        for (int j = 0; j < 16; j++) a2[j] = bb[j];
    }
    const int w1off = OW1 + half * 32;
#pragma unroll 8
    for (int c = 0; c < 64; c++)
        accum_row<16>(a2, sm + w1off + c * 64, hq[hrow + c]);
    __syncthreads();                                // all h1 reads done
#pragma unroll
    for (int j = 0; j < 16; j++) {
        float2 v = unpk(a2[j]);
        hq[hrow + half * 32 + 2 * j + 0] = lrelu(v.x);
        hq[hrow + half * 32 + 2 * j + 1] = lrelu(v.y);
    }
    __syncthreads();                                // h2 complete

    // ---- layer 3: 64 -> 128 (outs [half*64, half*64+64), 2 chunks of 32) ----
    float* pool = sm + OPOOLV2 + qlocal * 128 + half * 64;
#pragma unroll
    for (int ch = 0; ch < 2; ch++) {
        ull a3[16];
        {
            const ull* bb = (const ull*)(sm + OB2) + half * 32 + ch * 16;
#pragma unroll
            for (int j = 0; j < 16; j++) a3[j] = bb[j];
        }
        const int w2off = OW2 + half * 64 + ch * 32;
#pragma unroll 8
        for (int c = 0; c < 64; c++)
            accum_row<16>(a3, sm + w2off + c * 128, hq[hrow + c]);
#pragma unroll
        for (int j = 0; j < 16; j++) {
            float2 v = unpk(a3[j]);
            float v0 = lrelu(v.x);
            float v1 = lrelu(v.y);
#pragma unroll
            for (int o = 16; o > 0; o >>= 1) {
                v0 = fmaxf(v0, __shfl_down_sync(0xffffffffu, v0, o));
                v1 = fmaxf(v1, __shfl_down_sync(0xffffffffu, v1, o));
            }
            if (lane == 0) {
                pool[ch * 32 + 2 * j + 0] = v0;
                pool[ch * 32 + 2 * j + 1] = v1;
            }
        }
    }
    __syncwarp();
    if (lane < 16) {
        float4* dst = (float4*)(out + BB * NQ * 3 + (size_t)q * 128 + half * 64);
        dst[lane] = ((const float4*)pool)[lane];
    }
}

// ---------------------------------------------------------------------------
extern "C" void kernel_launch(void* const* d_in, const int* in_sizes, int n_in,
                              void* d_out, int out_size)
{
    const float* xyz  = (const float*)d_in[0];
    const float* feat = (const float*)d_in[1];
    const float* W0   = (const float*)d_in[2];
    const float* b0   = (const float*)d_in[3];
    const float* W1   = (const float*)d_in[4];
    const float* b1   = (const float*)d_in[5];
    const float* W2   = (const float*)d_in[6];
    const float* b2   = (const float*)d_in[7];
    float* out = (float*)d_out;

    cudaFuncSetAttribute(fps_kernel, cudaFuncAttributeMaxDynamicSharedMemorySize,
                         3 * NP * 4);
    cudaFuncSetAttribute(mlp_kernel, cudaFuncAttributeMaxDynamicSharedMemorySize,
                         SMEM_MLP_BYTES);

    fps_kernel<<<BB, 1024, 3 * NP * 4>>>(xyz, out);
    knn_kernel<<<(BB * NQ) / 8, 256>>>(xyz, out);
    mlp_kernel<<<(BB * NQ) / 4, 256, SMEM_MLP_BYTES>>>(xyz, feat, W0, b0, W1, b1,
                                                       W2, b2, out);
}